// round 1
// baseline (speedup 1.0000x reference)
#include <cuda_runtime.h>
#include <math.h>

// Problem constants (fixed shapes for this problem instance)
#define BB   4
#define SS   1024
#define HH   32
#define KVHH 8
#define GG   4
#define DD   128
#define QT   64
#define KT   64
#define WIN  512
#define NTHREADS 256

#define QS_STRIDE 132   // float4-aligned rows, conflict-free for 2-addr broadcast reads
#define KS_STRIDE 129   // odd stride -> scalar reads across k-rows are ~2-way at worst
#define VS_STRIDE 132   // float4-aligned rows for vectorized V reads
#define PS_STRIDE 65

struct Smem {
    float Qs[QT][QS_STRIDE];
    float Ks[KT][KS_STRIDE];
    float Vs[KT][VS_STRIDE];
    float Ps[QT][PS_STRIDE];
    float m_s[QT];
    float l_s[QT];
    float alpha_s[QT];
};

__global__ __launch_bounds__(NTHREADS, 1)
void attn_kernel(const float* __restrict__ q,
                 const float* __restrict__ kk,
                 const float* __restrict__ vv,
                 float* __restrict__ out)
{
    extern __shared__ char smem_raw[];
    Smem& sm = *reinterpret_cast<Smem*>(smem_raw);

    const int qt  = blockIdx.x;       // query tile index (0..15)
    const int h   = blockIdx.y;       // head (0..31)
    const int b   = blockIdx.z;       // batch (0..3)
    const int kvh = h / GG;
    const int q0  = qt * QT;
    const int tid = threadIdx.x;

    const float scale = 0.08838834764831843f;   // 1/sqrt(128)

    // ---- load Q tile: 64 rows x 128 dims, head h ----
    #pragma unroll
    for (int it = 0; it < (QT * DD / 4) / NTHREADS; it++) {   // 8 iters
        int idx = tid + it * NTHREADS;
        int r   = idx >> 5;          // row 0..63
        int c4  = idx & 31;          // float4 col 0..31
        float4 val = *(const float4*)&q[((size_t)((b * SS + q0 + r) * HH + h)) * DD + 4 * c4];
        *(float4*)&sm.Qs[r][4 * c4] = val;
    }
    if (tid < QT) { sm.m_s[tid] = -1e30f; sm.l_s[tid] = 0.0f; }

    // PV accumulator: rows 4*tz+i (i<4), dims {4*tw+c} and {64+4*tw+c} (c<4)
    float acc[4][8];
    #pragma unroll
    for (int i = 0; i < 4; i++)
        #pragma unroll
        for (int c = 0; c < 8; c++) acc[i][c] = 0.0f;

    const int ty = tid >> 4;   // 0..15 : q micro-row group (QK)
    const int tx = tid & 15;   // 0..15 : k micro-col group (QK)
    const int tz = ty;         // 0..15 : q micro-row group (PV)
    const int tw = tx;         // 0..15 : d group (PV)

    const int kt_begin = (qt - 8 > 0) ? (qt - 8) : 0;

    for (int kt = kt_begin; kt <= qt; kt++) {
        __syncthreads();   // previous tile fully consumed (also covers Q load / stat init)
        const int j0 = kt * KT;

        // ---- load K tile (scalar STS, odd stride) and V tile (vector STS) ----
        #pragma unroll
        for (int it = 0; it < (KT * DD / 4) / NTHREADS; it++) {   // 8 iters
            int idx = tid + it * NTHREADS;
            int r   = idx >> 5;
            int c4  = idx & 31;
            float4 kv = *(const float4*)&kk[((size_t)((b * SS + j0 + r) * KVHH + kvh)) * DD + 4 * c4];
            sm.Ks[r][4 * c4 + 0] = kv.x;
            sm.Ks[r][4 * c4 + 1] = kv.y;
            sm.Ks[r][4 * c4 + 2] = kv.z;
            sm.Ks[r][4 * c4 + 3] = kv.w;
            float4 vval = *(const float4*)&vv[((size_t)((b * SS + j0 + r) * KVHH + kvh)) * DD + 4 * c4];
            *(float4*)&sm.Vs[r][4 * c4] = vval;
        }
        __syncthreads();

        // ---- S = Q K^T  (64x64, k-dim 128), 4x4 micro-tile per thread ----
        float s_acc[4][4];
        #pragma unroll
        for (int i = 0; i < 4; i++)
            #pragma unroll
            for (int j = 0; j < 4; j++) s_acc[i][j] = 0.0f;

        #pragma unroll 8
        for (int d = 0; d < DD; d++) {
            float qf[4], kf[4];
            #pragma unroll
            for (int i = 0; i < 4; i++) qf[i] = sm.Qs[4 * ty + i][d];
            #pragma unroll
            for (int j = 0; j < 4; j++) kf[j] = sm.Ks[4 * tx + j][d];
            #pragma unroll
            for (int i = 0; i < 4; i++)
                #pragma unroll
                for (int j = 0; j < 4; j++) s_acc[i][j] = fmaf(qf[i], kf[j], s_acc[i][j]);
        }

        // epilogue: scale, softcap, mask -> Ps
        #pragma unroll
        for (int i = 0; i < 4; i++) {
            const int ig = q0 + 4 * ty + i;
            #pragma unroll
            for (int j = 0; j < 4; j++) {
                const int jg = j0 + 4 * tx + j;
                float s = s_acc[i][j] * scale;
                s = 50.0f * tanhf(s * 0.02f);
                const bool valid = (jg <= ig) && ((ig - jg) < WIN);
                sm.Ps[4 * ty + i][4 * tx + j] = valid ? s : -1e30f;
            }
        }
        __syncthreads();

        // ---- online softmax: 4 threads per row ----
        {
            const int row  = tid >> 2;
            const int part = tid & 3;
            float sv[16];
            float lmax = -1e30f;
            #pragma unroll
            for (int c = 0; c < 16; c++) {
                sv[c] = sm.Ps[row][part * 16 + c];
                lmax = fmaxf(lmax, sv[c]);
            }
            lmax = fmaxf(lmax, __shfl_xor_sync(0xffffffffu, lmax, 1));
            lmax = fmaxf(lmax, __shfl_xor_sync(0xffffffffu, lmax, 2));
            const float m_old = sm.m_s[row];
            const float m_new = fmaxf(m_old, lmax);
            const float alpha = __expf(m_old - m_new);
            float lsum = 0.0f;
            #pragma unroll
            for (int c = 0; c < 16; c++) {
                float p = (sv[c] < -1e29f) ? 0.0f : __expf(sv[c] - m_new);
                sm.Ps[row][part * 16 + c] = p;
                lsum += p;
            }
            lsum += __shfl_xor_sync(0xffffffffu, lsum, 1);
            lsum += __shfl_xor_sync(0xffffffffu, lsum, 2);
            if (part == 0) {
                sm.m_s[row]     = m_new;
                sm.l_s[row]     = sm.l_s[row] * alpha + lsum;
                sm.alpha_s[row] = alpha;
            }
        }
        __syncthreads();

        // ---- PV: acc = acc*alpha + P @ V ----
        {
            float al[4];
            #pragma unroll
            for (int i = 0; i < 4; i++) al[i] = sm.alpha_s[4 * tz + i];
            #pragma unroll
            for (int i = 0; i < 4; i++)
                #pragma unroll
                for (int c = 0; c < 8; c++) acc[i][c] *= al[i];

            #pragma unroll 4
            for (int t = 0; t < KT; t++) {
                float pf[4];
                #pragma unroll
                for (int i = 0; i < 4; i++) pf[i] = sm.Ps[4 * tz + i][t];
                float4 va = *(const float4*)&sm.Vs[t][4 * tw];
                float4 vb = *(const float4*)&sm.Vs[t][64 + 4 * tw];
                #pragma unroll
                for (int i = 0; i < 4; i++) {
                    acc[i][0] = fmaf(pf[i], va.x, acc[i][0]);
                    acc[i][1] = fmaf(pf[i], va.y, acc[i][1]);
                    acc[i][2] = fmaf(pf[i], va.z, acc[i][2]);
                    acc[i][3] = fmaf(pf[i], va.w, acc[i][3]);
                    acc[i][4] = fmaf(pf[i], vb.x, acc[i][4]);
                    acc[i][5] = fmaf(pf[i], vb.y, acc[i][5]);
                    acc[i][6] = fmaf(pf[i], vb.z, acc[i][6]);
                    acc[i][7] = fmaf(pf[i], vb.w, acc[i][7]);
                }
            }
        }
    }

    // ---- write output: out[token][h][d] = acc / l ----
    #pragma unroll
    for (int i = 0; i < 4; i++) {
        const int r   = 4 * tz + i;
        const float inv = 1.0f / sm.l_s[r];
        const size_t base = ((size_t)((b * SS + q0 + r) * HH + h)) * DD;
        float4 o1 = make_float4(acc[i][0] * inv, acc[i][1] * inv, acc[i][2] * inv, acc[i][3] * inv);
        float4 o2 = make_float4(acc[i][4] * inv, acc[i][5] * inv, acc[i][6] * inv, acc[i][7] * inv);
        *(float4*)&out[base + 4 * tw]      = o1;
        *(float4*)&out[base + 64 + 4 * tw] = o2;
    }
}

extern "C" void kernel_launch(void* const* d_in, const int* in_sizes, int n_in,
                              void* d_out, int out_size)
{
    const float* q  = (const float*)d_in[0];   // query  [4096,32,128]
    const float* k  = (const float*)d_in[1];   // key    [4096, 8,128]
    const float* v  = (const float*)d_in[2];   // value  [4096, 8,128]
    // d_in[3] k_cache, d_in[4] v_cache, d_in[5] block_offsets:
    // output is independent of them (cache write-then-gather of the same
    // permutation blocks returns key/value unchanged), so they are unused.
    float* out = (float*)d_out;

    cudaFuncSetAttribute(attn_kernel,
                         cudaFuncAttributeMaxDynamicSharedMemorySize,
                         (int)sizeof(Smem));

    dim3 grid(SS / QT, HH, BB);   // 16 x 32 x 4 = 2048 blocks
    attn_kernel<<<grid, NTHREADS, sizeof(Smem)>>>(q, k, v, out);
}

// round 2
// speedup vs baseline: 2.4389x; 2.4389x over previous
#include <cuda_runtime.h>
#include <math.h>
#include <stdint.h>

// Problem constants
#define BB   4
#define SS   1024
#define HH   32
#define KVHH 8
#define GG   4
#define DD   128
#define QT   64
#define KT   64
#define WIN  512
#define NTHREADS 256

// Smem strides (floats). Chosen so every mma fragment load is bank-conflict-free.
#define QS_STRIDE 132
#define KS_STRIDE 132
#define VS_STRIDE 136
#define PS_STRIDE 68

struct Smem {
    float Qs[QT][QS_STRIDE];
    float Ks[KT][KS_STRIDE];
    float Vs[KT][VS_STRIDE];
    float Ps[QT][PS_STRIDE];
    float m_s[QT];
    float l_s[QT];
    float alpha_s[QT];
};

__device__ __forceinline__ uint32_t f2tf32(float x) {
    uint32_t y;
    asm("cvt.rna.tf32.f32 %0, %1;" : "=r"(y) : "f"(x));
    return y;
}
__device__ __forceinline__ float tanh_fast(float x) {
    float y;
    asm("tanh.approx.f32 %0, %1;" : "=f"(y) : "f"(x));
    return y;
}
__device__ __forceinline__ void mma_tf32(float* d, const uint32_t* a, const uint32_t* b) {
    asm volatile(
        "mma.sync.aligned.m16n8k8.row.col.f32.tf32.tf32.f32 "
        "{%0,%1,%2,%3}, {%4,%5,%6,%7}, {%8,%9}, {%0,%1,%2,%3};"
        : "+f"(d[0]), "+f"(d[1]), "+f"(d[2]), "+f"(d[3])
        : "r"(a[0]), "r"(a[1]), "r"(a[2]), "r"(a[3]), "r"(b[0]), "r"(b[1]));
}
__device__ __forceinline__ uint32_t ldu(const float* p) {
    return __float_as_uint(*p);
}

__global__ __launch_bounds__(NTHREADS, 1)
void attn_kernel(const float* __restrict__ q,
                 const float* __restrict__ kk,
                 const float* __restrict__ vv,
                 float* __restrict__ out)
{
    extern __shared__ char smem_raw[];
    Smem& sm = *reinterpret_cast<Smem*>(smem_raw);

    const int qt  = blockIdx.x;       // query tile (0..15)
    const int h   = blockIdx.y;       // head (0..31)
    const int b   = blockIdx.z;       // batch (0..3)
    const int kvh = h / GG;
    const int q0  = qt * QT;
    const int tid = threadIdx.x;
    const int lane = tid & 31;
    const int wid  = tid >> 5;
    const int g    = lane >> 2;       // mma groupID (row within 8)
    const int tg   = lane & 3;        // mma threadID-in-group

    const float scale = 0.08838834764831843f;   // 1/sqrt(128)

    // ---- load Q tile (tf32-rounded) ----
    #pragma unroll
    for (int it = 0; it < (QT * DD / 4) / NTHREADS; it++) {   // 8 iters
        int idx = tid + it * NTHREADS;
        int r   = idx >> 5;
        int c4  = idx & 31;
        float4 val = *(const float4*)&q[((size_t)((b * SS + q0 + r) * HH + h)) * DD + 4 * c4];
        sm.Qs[r][4 * c4 + 0] = __uint_as_float(f2tf32(val.x));
        sm.Qs[r][4 * c4 + 1] = __uint_as_float(f2tf32(val.y));
        sm.Qs[r][4 * c4 + 2] = __uint_as_float(f2tf32(val.z));
        sm.Qs[r][4 * c4 + 3] = __uint_as_float(f2tf32(val.w));
    }
    if (tid < QT) { sm.m_s[tid] = -1e30f; sm.l_s[tid] = 0.0f; }

    // mma warp partitions
    const int wr   = wid >> 1;   // 0..3 : 16-row group (both QK and PV)
    const int wcol = wid & 1;    // 0..1 : 32-col group (QK) / 64-dim group (PV)

    // Output accumulator: rows {16*wr+g, +8}, dims 64*wcol + 8*t + 2*tg + {0,1}
    float o[8][4];
    #pragma unroll
    for (int t = 0; t < 8; t++)
        #pragma unroll
        for (int c = 0; c < 4; c++) o[t][c] = 0.0f;

    const int kt_begin = (qt - 8 > 0) ? (qt - 8) : 0;

    for (int kt = kt_begin; kt <= qt; kt++) {
        __syncthreads();   // prev iter fully consumed (covers Q load / stat init too)
        const int j0 = kt * KT;

        // ---- load K/V tile (tf32-rounded) ----
        #pragma unroll
        for (int it = 0; it < (KT * DD / 4) / NTHREADS; it++) {
            int idx = tid + it * NTHREADS;
            int r   = idx >> 5;
            int c4  = idx & 31;
            const size_t gbase = ((size_t)((b * SS + j0 + r) * KVHH + kvh)) * DD + 4 * c4;
            float4 kvv = *(const float4*)&kk[gbase];
            sm.Ks[r][4 * c4 + 0] = __uint_as_float(f2tf32(kvv.x));
            sm.Ks[r][4 * c4 + 1] = __uint_as_float(f2tf32(kvv.y));
            sm.Ks[r][4 * c4 + 2] = __uint_as_float(f2tf32(kvv.z));
            sm.Ks[r][4 * c4 + 3] = __uint_as_float(f2tf32(kvv.w));
            float4 vvv = *(const float4*)&vv[gbase];
            sm.Vs[r][4 * c4 + 0] = __uint_as_float(f2tf32(vvv.x));
            sm.Vs[r][4 * c4 + 1] = __uint_as_float(f2tf32(vvv.y));
            sm.Vs[r][4 * c4 + 2] = __uint_as_float(f2tf32(vvv.z));
            sm.Vs[r][4 * c4 + 3] = __uint_as_float(f2tf32(vvv.w));
        }
        __syncthreads();

        // ---- S = Q K^T via mma tf32: warp computes 16x32 ----
        float s[4][4];
        #pragma unroll
        for (int t = 0; t < 4; t++)
            #pragma unroll
            for (int c = 0; c < 4; c++) s[t][c] = 0.0f;

        const int ar = 16 * wr + g;
        #pragma unroll
        for (int k0 = 0; k0 < DD; k0 += 8) {
            uint32_t a[4];
            a[0] = ldu(&sm.Qs[ar][k0 + tg]);
            a[1] = ldu(&sm.Qs[ar + 8][k0 + tg]);
            a[2] = ldu(&sm.Qs[ar][k0 + tg + 4]);
            a[3] = ldu(&sm.Qs[ar + 8][k0 + tg + 4]);
            #pragma unroll
            for (int t = 0; t < 4; t++) {
                const int n0 = 32 * wcol + 8 * t;
                uint32_t bfr[2];
                bfr[0] = ldu(&sm.Ks[n0 + g][k0 + tg]);
                bfr[1] = ldu(&sm.Ks[n0 + g][k0 + tg + 4]);
                mma_tf32(s[t], a, bfr);
            }
        }

        // ---- epilogue: scale, softcap, mask -> Ps ----
        #pragma unroll
        for (int t = 0; t < 4; t++) {
            const int c0 = 32 * wcol + 8 * t + 2 * tg;
            #pragma unroll
            for (int half = 0; half < 2; half++) {
                const int r  = ar + 8 * half;
                const int ig = q0 + r;
                float v0 = s[t][2 * half + 0] * scale;
                float v1 = s[t][2 * half + 1] * scale;
                v0 = 50.0f * tanh_fast(v0 * 0.02f);
                v1 = 50.0f * tanh_fast(v1 * 0.02f);
                const int jg0 = j0 + c0;
                const bool ok0 = (jg0 <= ig) && ((ig - jg0) < WIN);
                const bool ok1 = (jg0 + 1 <= ig) && ((ig - jg0 - 1) < WIN);
                float2 st = make_float2(ok0 ? v0 : -1e30f, ok1 ? v1 : -1e30f);
                *(float2*)&sm.Ps[r][c0] = st;
            }
        }
        __syncthreads();

        // ---- online softmax: 4 threads per row ----
        {
            const int row  = tid >> 2;
            const int part = tid & 3;
            float sv[16];
            float lmax = -1e30f;
            #pragma unroll
            for (int c = 0; c < 16; c++) {
                sv[c] = sm.Ps[row][part * 16 + c];
                lmax = fmaxf(lmax, sv[c]);
            }
            lmax = fmaxf(lmax, __shfl_xor_sync(0xffffffffu, lmax, 1));
            lmax = fmaxf(lmax, __shfl_xor_sync(0xffffffffu, lmax, 2));
            const float m_old = sm.m_s[row];
            const float m_new = fmaxf(m_old, lmax);
            const float alpha = __expf(m_old - m_new);
            float lsum = 0.0f;
            #pragma unroll
            for (int c = 0; c < 16; c++) {
                float p = (sv[c] < -1e29f) ? 0.0f : __expf(sv[c] - m_new);
                sm.Ps[row][part * 16 + c] = __uint_as_float(f2tf32(p));
                lsum += p;
            }
            lsum += __shfl_xor_sync(0xffffffffu, lsum, 1);
            lsum += __shfl_xor_sync(0xffffffffu, lsum, 2);
            if (part == 0) {
                sm.m_s[row]     = m_new;
                sm.l_s[row]     = sm.l_s[row] * alpha + lsum;
                sm.alpha_s[row] = alpha;
            }
        }
        __syncthreads();

        // ---- PV: o = o*alpha + P @ V via mma tf32: warp computes 16x64 ----
        {
            const float al0 = sm.alpha_s[16 * wr + g];
            const float al1 = sm.alpha_s[16 * wr + g + 8];
            #pragma unroll
            for (int t = 0; t < 8; t++) {
                o[t][0] *= al0; o[t][1] *= al0;
                o[t][2] *= al1; o[t][3] *= al1;
            }
            #pragma unroll
            for (int k0 = 0; k0 < KT; k0 += 8) {
                uint32_t a[4];
                a[0] = ldu(&sm.Ps[16 * wr + g][k0 + tg]);
                a[1] = ldu(&sm.Ps[16 * wr + g + 8][k0 + tg]);
                a[2] = ldu(&sm.Ps[16 * wr + g][k0 + tg + 4]);
                a[3] = ldu(&sm.Ps[16 * wr + g + 8][k0 + tg + 4]);
                #pragma unroll
                for (int t = 0; t < 8; t++) {
                    const int n0 = 64 * wcol + 8 * t;
                    uint32_t bfr[2];
                    bfr[0] = ldu(&sm.Vs[k0 + tg][n0 + g]);
                    bfr[1] = ldu(&sm.Vs[k0 + tg + 4][n0 + g]);
                    mma_tf32(o[t], a, bfr);
                }
            }
        }
    }

    // ---- write output ----
    {
        const int r0 = 16 * wr + g;
        const int r1 = r0 + 8;
        const float inv0 = 1.0f / sm.l_s[r0];
        const float inv1 = 1.0f / sm.l_s[r1];
        const size_t base0 = ((size_t)((b * SS + q0 + r0) * HH + h)) * DD;
        const size_t base1 = ((size_t)((b * SS + q0 + r1) * HH + h)) * DD;
        #pragma unroll
        for (int t = 0; t < 8; t++) {
            const int col = 64 * wcol + 8 * t + 2 * tg;
            float2 w0 = make_float2(o[t][0] * inv0, o[t][1] * inv0);
            float2 w1 = make_float2(o[t][2] * inv1, o[t][3] * inv1);
            *(float2*)&out[base0 + col] = w0;
            *(float2*)&out[base1 + col] = w1;
        }
    }
}

extern "C" void kernel_launch(void* const* d_in, const int* in_sizes, int n_in,
                              void* d_out, int out_size)
{
    const float* q  = (const float*)d_in[0];   // query  [4096,32,128]
    const float* k  = (const float*)d_in[1];   // key    [4096, 8,128]
    const float* v  = (const float*)d_in[2];   // value  [4096, 8,128]
    // d_in[3..5] (caches + block table) do not affect the output: the cache
    // write-then-gather of the same permutation blocks returns key/value unchanged.
    float* out = (float*)d_out;

    cudaFuncSetAttribute(attn_kernel,
                         cudaFuncAttributeMaxDynamicSharedMemorySize,
                         (int)sizeof(Smem));

    dim3 grid(SS / QT, HH, BB);   // 16 x 32 x 4 = 2048 blocks
    attn_kernel<<<grid, NTHREADS, sizeof(Smem)>>>(q, k, v, out);
}

// round 3
// speedup vs baseline: 3.7166x; 1.5239x over previous
#include <cuda_runtime.h>
#include <stdint.h>

#define BB 4
#define SS 1024
#define HH 32
#define KVHH 8
#define DD 128
#define QTILE 128
#define KTILE 64
#define WIN 512
#define NT 256

// smem pitches (in floats) — chosen for conflict-free fragment access
#define QP 136
#define KP 136
#define VP 132

#define QS_OFF 0
#define KS_OFF (QTILE * QP)                    // 17408
#define VS_OFF (KS_OFF + 2 * KTILE * KP)       // 34816
#define SMEM_FLOATS (VS_OFF + 2 * KTILE * VP)  // 51712 floats = 206848 B

__device__ __forceinline__ float tanh_fast(float x) {
    float y; asm("tanh.approx.f32 %0, %1;" : "=f"(y) : "f"(x)); return y;
}
__device__ __forceinline__ float ex2(float x) {
    float y; asm("ex2.approx.f32 %0, %1;" : "=f"(y) : "f"(x)); return y;
}
__device__ __forceinline__ uint32_t f2tf(float x) {
    uint32_t y; asm("cvt.rna.tf32.f32 %0, %1;" : "=r"(y) : "f"(x)); return y;
}
__device__ __forceinline__ void mma8(float* d, uint32_t a0, uint32_t a1, uint32_t a2, uint32_t a3,
                                     uint32_t b0, uint32_t b1) {
    asm volatile(
        "mma.sync.aligned.m16n8k8.row.col.f32.tf32.tf32.f32 "
        "{%0,%1,%2,%3}, {%4,%5,%6,%7}, {%8,%9}, {%0,%1,%2,%3};"
        : "+f"(d[0]), "+f"(d[1]), "+f"(d[2]), "+f"(d[3])
        : "r"(a0), "r"(a1), "r"(a2), "r"(a3), "r"(b0), "r"(b1));
}
__device__ __forceinline__ void cp16(uint32_t dst, const float* src) {
    asm volatile("cp.async.cg.shared.global [%0], [%1], 16;" :: "r"(dst), "l"(src));
}
__device__ __forceinline__ uint32_t fb(float x) { return __float_as_uint(x); }

__global__ __launch_bounds__(NT, 1)
void attn_kernel(const float* __restrict__ q,
                 const float* __restrict__ kk,
                 const float* __restrict__ vv,
                 float* __restrict__ out)
{
    extern __shared__ float sm[];
    uint32_t smb;
    asm("{ .reg .u64 t; cvta.to.shared.u64 t, %1; cvt.u32.u64 %0, t; }" : "=r"(smb) : "l"(sm));

    const int qt = blockIdx.x, h = blockIdx.y, b = blockIdx.z;
    const int kvh = h >> 2;
    const int q0  = qt * QTILE;
    const int tid = threadIdx.x, lane = tid & 31, w = tid >> 5;
    const int g = lane >> 2, tg = lane & 3;

    const int lo = (q0 - WIN + 1 > 0) ? ((q0 - WIN + 1) >> 6) : 0;
    const int hi = (q0 + QTILE - 1) >> 6;

    // ---- prologue: cp.async K/V tile 'lo' into buffer 0 ----
    {
        const int j0 = lo * KTILE;
        #pragma unroll
        for (int it = 0; it < 8; it++) {
            int idx = tid + it * NT;
            int r = idx >> 5, c4 = idx & 31;
            const size_t gidx = ((size_t)((b * SS + j0 + r) * KVHH + kvh)) * DD + 4 * c4;
            cp16(smb + (uint32_t)(KS_OFF + r * KP + 4 * c4) * 4, kk + gidx);
            cp16(smb + (uint32_t)(VS_OFF + r * VP + 4 * c4) * 4, vv + gidx);
        }
        asm volatile("cp.async.commit_group;");
    }

    // ---- load Q tile (pre-scaled by scale/softcap, tf32-rounded) ----
    const float qscale = 0.08838834764831843f * 0.02f;   // (1/sqrt(128)) / 50
    #pragma unroll
    for (int it = 0; it < 16; it++) {
        int idx = tid + it * NT;
        int r = idx >> 5, c4 = idx & 31;
        float4 val = *(const float4*)&q[((size_t)((b * SS + q0 + r) * HH + h)) * DD + 4 * c4];
        uint4 o4;
        o4.x = f2tf(val.x * qscale); o4.y = f2tf(val.y * qscale);
        o4.z = f2tf(val.z * qscale); o4.w = f2tf(val.w * qscale);
        *(uint4*)&sm[QS_OFF + r * QP + 4 * c4] = o4;
    }

    float o[16][4];
    #pragma unroll
    for (int t = 0; t < 16; t++) { o[t][0] = 0.f; o[t][1] = 0.f; o[t][2] = 0.f; o[t][3] = 0.f; }
    float m0 = -1e30f, m1 = -1e30f, l0 = 0.f, l1 = 0.f;

    const int rlo = q0 + 16 * w, rhi = rlo + 15;
    const int ig0 = rlo + g, ig1 = ig0 + 8;
    const float LOG2E = 1.4426950408889634f;

    for (int kt = lo; kt <= hi; kt++) {
        const int buf = (kt - lo) & 1;
        if (kt < hi) {
            const int j0n = (kt + 1) * KTILE;
            #pragma unroll
            for (int it = 0; it < 8; it++) {
                int idx = tid + it * NT;
                int r = idx >> 5, c4 = idx & 31;
                const size_t gidx = ((size_t)((b * SS + j0n + r) * KVHH + kvh)) * DD + 4 * c4;
                cp16(smb + (uint32_t)(KS_OFF + (buf ^ 1) * KTILE * KP + r * KP + 4 * c4) * 4, kk + gidx);
                cp16(smb + (uint32_t)(VS_OFF + (buf ^ 1) * KTILE * VP + r * VP + 4 * c4) * 4, vv + gidx);
            }
            asm volatile("cp.async.commit_group;");
            asm volatile("cp.async.wait_group 1;");
        } else {
            asm volatile("cp.async.wait_group 0;");
        }
        __syncthreads();

        const int j0 = kt * KTILE;
        const bool active = (j0 <= rhi) && (j0 + KTILE - 1 >= rlo - WIN + 1);
        if (active) {
            const float* Ks = sm + KS_OFF + buf * KTILE * KP;
            const float* Vs = sm + VS_OFF + buf * KTILE * VP;
            const float* Qw = sm + QS_OFF + (16 * w + g) * QP;

            // ---- S = Q K^T (k-relabeled tf32 mma, float2 fragment loads) ----
            float s[8][4];
            #pragma unroll
            for (int t = 0; t < 8; t++) { s[t][0] = 0.f; s[t][1] = 0.f; s[t][2] = 0.f; s[t][3] = 0.f; }

            #pragma unroll
            for (int k0 = 0; k0 < 16; k0++) {
                float2 a0 = *(const float2*)(Qw + 8 * k0 + 2 * tg);
                float2 a1 = *(const float2*)(Qw + 8 * QP + 8 * k0 + 2 * tg);
                #pragma unroll
                for (int t = 0; t < 8; t++) {
                    float2 kb = *(const float2*)(Ks + (8 * t + g) * KP + 8 * k0 + 2 * tg);
                    mma8(s[t], fb(a0.x), fb(a1.x), fb(a0.y), fb(a1.y), fb(kb.x), fb(kb.y));
                }
            }

            // ---- softcap + mask + in-register online softmax ----
            float rmax0 = -1e30f, rmax1 = -1e30f;
            #pragma unroll
            for (int t = 0; t < 8; t++) {
                const int jg = j0 + 8 * t + 2 * tg;
                float v0 = 50.f * tanh_fast(s[t][0]);
                float v1 = 50.f * tanh_fast(s[t][1]);
                float v2 = 50.f * tanh_fast(s[t][2]);
                float v3 = 50.f * tanh_fast(s[t][3]);
                bool ok0 = (jg     <= ig0) && (ig0 - jg     < WIN);
                bool ok1 = (jg + 1 <= ig0) && (ig0 - jg - 1 < WIN);
                bool ok2 = (jg     <= ig1) && (ig1 - jg     < WIN);
                bool ok3 = (jg + 1 <= ig1) && (ig1 - jg - 1 < WIN);
                s[t][0] = ok0 ? v0 : -1e30f;
                s[t][1] = ok1 ? v1 : -1e30f;
                s[t][2] = ok2 ? v2 : -1e30f;
                s[t][3] = ok3 ? v3 : -1e30f;
                rmax0 = fmaxf(rmax0, fmaxf(s[t][0], s[t][1]));
                rmax1 = fmaxf(rmax1, fmaxf(s[t][2], s[t][3]));
            }
            rmax0 = fmaxf(rmax0, __shfl_xor_sync(0xffffffffu, rmax0, 1));
            rmax0 = fmaxf(rmax0, __shfl_xor_sync(0xffffffffu, rmax0, 2));
            rmax1 = fmaxf(rmax1, __shfl_xor_sync(0xffffffffu, rmax1, 1));
            rmax1 = fmaxf(rmax1, __shfl_xor_sync(0xffffffffu, rmax1, 2));

            const float m0n = fmaxf(m0, rmax0);
            const float m1n = fmaxf(m1, rmax1);
            const float al0 = ex2((m0 - m0n) * LOG2E);
            const float al1 = ex2((m1 - m1n) * LOG2E);
            m0 = m0n; m1 = m1n;

            float ls0 = 0.f, ls1 = 0.f;
            #pragma unroll
            for (int t = 0; t < 8; t++) {
                float p0 = (s[t][0] > -1e29f) ? ex2((s[t][0] - m0n) * LOG2E) : 0.f;
                float p1 = (s[t][1] > -1e29f) ? ex2((s[t][1] - m0n) * LOG2E) : 0.f;
                float p2 = (s[t][2] > -1e29f) ? ex2((s[t][2] - m1n) * LOG2E) : 0.f;
                float p3 = (s[t][3] > -1e29f) ? ex2((s[t][3] - m1n) * LOG2E) : 0.f;
                s[t][0] = p0; s[t][1] = p1; s[t][2] = p2; s[t][3] = p3;
                ls0 += p0 + p1; ls1 += p2 + p3;
            }
            ls0 += __shfl_xor_sync(0xffffffffu, ls0, 1);
            ls0 += __shfl_xor_sync(0xffffffffu, ls0, 2);
            ls1 += __shfl_xor_sync(0xffffffffu, ls1, 1);
            ls1 += __shfl_xor_sync(0xffffffffu, ls1, 2);
            l0 = l0 * al0 + ls0;
            l1 = l1 * al1 + ls1;

            #pragma unroll
            for (int t = 0; t < 16; t++) {
                o[t][0] *= al0; o[t][1] *= al0; o[t][2] *= al1; o[t][3] *= al1;
            }

            // ---- PV: A-fragment == S C-fragment (free), conflict-free V reads ----
            #pragma unroll
            for (int kg = 0; kg < 8; kg++) {
                const uint32_t a0 = fb(s[kg][0]), a1 = fb(s[kg][2]);
                const uint32_t a2 = fb(s[kg][1]), a3 = fb(s[kg][3]);
                const float* Vr0 = Vs + (8 * kg + 2 * tg) * VP;
                const float* Vr1 = Vr0 + VP;
                #pragma unroll
                for (int t = 0; t < 16; t++) {
                    mma8(o[t], a0, a1, a2, a3, fb(Vr0[8 * t + g]), fb(Vr1[8 * t + g]));
                }
            }
        }
        __syncthreads();
    }

    // ---- write output ----
    const float inv0 = 1.f / l0;
    const float inv1 = 1.f / l1;
    const size_t base0 = ((size_t)((b * SS + ig0) * HH + h)) * DD;
    const size_t base1 = ((size_t)((b * SS + ig1) * HH + h)) * DD;
    #pragma unroll
    for (int t = 0; t < 16; t++) {
        const int col = 8 * t + 2 * tg;
        *(float2*)&out[base0 + col] = make_float2(o[t][0] * inv0, o[t][1] * inv0);
        *(float2*)&out[base1 + col] = make_float2(o[t][2] * inv1, o[t][3] * inv1);
    }
}

extern "C" void kernel_launch(void* const* d_in, const int* in_sizes, int n_in,
                              void* d_out, int out_size)
{
    const float* q = (const float*)d_in[0];   // query  [4096,32,128]
    const float* k = (const float*)d_in[1];   // key    [4096, 8,128]
    const float* v = (const float*)d_in[2];   // value  [4096, 8,128]
    // d_in[3..5] (caches + block table) do not affect the output: the cache
    // write-then-gather of the same permutation blocks returns key/value unchanged.
    float* out = (float*)d_out;

    cudaFuncSetAttribute(attn_kernel,
                         cudaFuncAttributeMaxDynamicSharedMemorySize,
                         SMEM_FLOATS * 4);

    dim3 grid(SS / QTILE, HH, BB);   // 8 x 32 x 4 = 1024 blocks
    attn_kernel<<<grid, NT, SMEM_FLOATS * 4>>>(q, k, v, out);
}

// round 5
// speedup vs baseline: 5.2746x; 1.4192x over previous
#include <cuda_runtime.h>
#include <cuda_fp16.h>
#include <stdint.h>

#define BB 4
#define SS 1024
#define HH 32
#define KVHH 8
#define DD 128
#define QTILE 128
#define KTILE 64
#define WIN 512
#define NT 256

// fp16 smem tiles, 256B rows (128 halves), 16B-chunk XOR swizzle (chunk ^= row&7)
#define QBYTES (128 * 256)
#define KBYTES (64 * 256)
#define SMEM_BYTES (QBYTES + 4 * KBYTES)   // 32KB + 64KB = 96KB

__device__ __forceinline__ uint32_t swadr(uint32_t base, int row, int chunk) {
    return base + row * 256 + ((chunk ^ (row & 7)) << 4);
}
__device__ __forceinline__ float tanh_fast(float x) {
    float y; asm("tanh.approx.f32 %0, %1;" : "=f"(y) : "f"(x)); return y;
}
__device__ __forceinline__ float ex2(float x) {
    float y; asm("ex2.approx.f32 %0, %1;" : "=f"(y) : "f"(x)); return y;
}
__device__ __forceinline__ uint32_t pk(float lo, float hi) {
    __half2 h = __floats2half2_rn(lo, hi);
    return *(uint32_t*)&h;
}
__device__ __forceinline__ void ldsm4(uint32_t& r0, uint32_t& r1, uint32_t& r2, uint32_t& r3, uint32_t a) {
    asm volatile("ldmatrix.sync.aligned.m8n8.x4.shared.b16 {%0,%1,%2,%3},[%4];"
                 : "=r"(r0), "=r"(r1), "=r"(r2), "=r"(r3) : "r"(a));
}
__device__ __forceinline__ void ldsm4t(uint32_t& r0, uint32_t& r1, uint32_t& r2, uint32_t& r3, uint32_t a) {
    asm volatile("ldmatrix.sync.aligned.m8n8.x4.trans.shared.b16 {%0,%1,%2,%3},[%4];"
                 : "=r"(r0), "=r"(r1), "=r"(r2), "=r"(r3) : "r"(a));
}
__device__ __forceinline__ void mma16(float* d, uint32_t a0, uint32_t a1, uint32_t a2, uint32_t a3,
                                      uint32_t b0, uint32_t b1) {
    asm volatile(
        "mma.sync.aligned.m16n8k16.row.col.f32.f16.f16.f32 "
        "{%0,%1,%2,%3}, {%4,%5,%6,%7}, {%8,%9}, {%0,%1,%2,%3};"
        : "+f"(d[0]), "+f"(d[1]), "+f"(d[2]), "+f"(d[3])
        : "r"(a0), "r"(a1), "r"(a2), "r"(a3), "r"(b0), "r"(b1));
}

__global__ __launch_bounds__(NT, 1)
void attn_kernel(const float* __restrict__ q,
                 const float* __restrict__ kk,
                 const float* __restrict__ vv,
                 float* __restrict__ out)
{
    extern __shared__ char smraw[];
    uint32_t smb;
    asm("{ .reg .u64 t; cvta.to.shared.u64 t, %1; cvt.u32.u64 %0, t; }" : "=r"(smb) : "l"(smraw));
    const uint32_t Qb = smb, Kb = smb + QBYTES, Vb = Kb + 2 * KBYTES;

    const int qt = blockIdx.x, h = blockIdx.y, b = blockIdx.z;
    const int kvh = h >> 2;
    const int q0  = qt * QTILE;
    const int tid = threadIdx.x, lane = tid & 31, w = tid >> 5;
    const int g = lane >> 2, tg = lane & 3;

    // loader coordinates (chunk constant per thread, row varies by iter)
    const int lr = tid >> 4;       // 0..15
    const int lc = tid & 15;       // chunk 0..15

    // per-lane ldmatrix row/chunk components
    const int rowA  = 16 * w + (lane & 7) + 8 * ((lane >> 3) & 1);
    const int cA    = lane >> 4;
    const int rowB  = (lane & 7) + 8 * (lane >> 4);
    const int cB    = (lane >> 3) & 1;
    const int rowV_ = (lane & 7) + 8 * ((lane >> 3) & 1);
    const int cV    = lane >> 4;

    const int lo = (q0 - WIN + 1 > 0) ? ((q0 - WIN + 1) >> 6) : 0;
    const int hi = (q0 + QTILE - 1) >> 6;

    const float qscale = 0.08838834764831843f;   // 1/sqrt(128)
    const float LOG2E  = 1.4426950408889634f;

    float4 kr[8], vr[8];

    // ---- prologue: LDG K/V tile 'lo' into regs ----
    {
        const int j0 = lo * KTILE;
        #pragma unroll
        for (int it = 0; it < 4; it++) {
            const int r = lr + 16 * it;
            const float* kp = kk + ((size_t)((b * SS + j0 + r) * KVHH + kvh)) * DD + 8 * lc;
            const float* vp = vv + ((size_t)((b * SS + j0 + r) * KVHH + kvh)) * DD + 8 * lc;
            kr[2 * it]     = *(const float4*)kp;
            kr[2 * it + 1] = *(const float4*)(kp + 4);
            vr[2 * it]     = *(const float4*)vp;
            vr[2 * it + 1] = *(const float4*)(vp + 4);
        }
    }
    // ---- Q: LDG -> scale -> fp16 -> swizzled STS ----
    #pragma unroll
    for (int it = 0; it < 8; it++) {
        const int r = lr + 16 * it;
        const float* qp = q + ((size_t)((b * SS + q0 + r) * HH + h)) * DD + 8 * lc;
        float4 f0 = *(const float4*)qp;
        float4 f1 = *(const float4*)(qp + 4);
        uint4 u;
        u.x = pk(f0.x * qscale, f0.y * qscale);
        u.y = pk(f0.z * qscale, f0.w * qscale);
        u.z = pk(f1.x * qscale, f1.y * qscale);
        u.w = pk(f1.z * qscale, f1.w * qscale);
        *(uint4*)(size_t)0;  // placeholder removed below
        asm volatile("st.shared.v4.b32 [%0], {%1,%2,%3,%4};"
                     :: "r"(swadr(Qb, r, lc)), "r"(u.x), "r"(u.y), "r"(u.z), "r"(u.w));
    }
    // ---- store K/V tile lo into buffer 0 ----
    #pragma unroll
    for (int it = 0; it < 4; it++) {
        const int r = lr + 16 * it;
        uint4 uk, uv;
        uk.x = pk(kr[2*it].x, kr[2*it].y);   uk.y = pk(kr[2*it].z, kr[2*it].w);
        uk.z = pk(kr[2*it+1].x, kr[2*it+1].y); uk.w = pk(kr[2*it+1].z, kr[2*it+1].w);
        uv.x = pk(vr[2*it].x, vr[2*it].y);   uv.y = pk(vr[2*it].z, vr[2*it].w);
        uv.z = pk(vr[2*it+1].x, vr[2*it+1].y); uv.w = pk(vr[2*it+1].z, vr[2*it+1].w);
        asm volatile("st.shared.v4.b32 [%0], {%1,%2,%3,%4};"
                     :: "r"(swadr(Kb, r, lc)), "r"(uk.x), "r"(uk.y), "r"(uk.z), "r"(uk.w));
        asm volatile("st.shared.v4.b32 [%0], {%1,%2,%3,%4};"
                     :: "r"(swadr(Vb, r, lc)), "r"(uv.x), "r"(uv.y), "r"(uv.z), "r"(uv.w));
    }
    __syncthreads();

    float o[16][4];
    #pragma unroll
    for (int t = 0; t < 16; t++) { o[t][0] = 0.f; o[t][1] = 0.f; o[t][2] = 0.f; o[t][3] = 0.f; }
    float m0 = -1e30f, m1 = -1e30f, l0 = 0.f, l1 = 0.f;

    const int rlo = q0 + 16 * w, rhi = rlo + 15;
    const int ig0 = rlo + g, ig1 = ig0 + 8;

    for (int kt = lo; kt <= hi; kt++) {
        const int cur = (kt - lo) & 1;
        // prefetch next tile into regs (latency hidden by compute below)
        if (kt < hi) {
            const int j0n = (kt + 1) * KTILE;
            #pragma unroll
            for (int it = 0; it < 4; it++) {
                const int r = lr + 16 * it;
                const float* kp = kk + ((size_t)((b * SS + j0n + r) * KVHH + kvh)) * DD + 8 * lc;
                const float* vp = vv + ((size_t)((b * SS + j0n + r) * KVHH + kvh)) * DD + 8 * lc;
                kr[2 * it]     = *(const float4*)kp;
                kr[2 * it + 1] = *(const float4*)(kp + 4);
                vr[2 * it]     = *(const float4*)vp;
                vr[2 * it + 1] = *(const float4*)(vp + 4);
            }
        }

        const int j0 = kt * KTILE;
        const bool active = (j0 <= rhi) && (j0 + KTILE - 1 >= rlo - WIN + 1);
        if (active) {
            const uint32_t Kc = Kb + cur * KBYTES;
            const uint32_t Vc = Vb + cur * KBYTES;

            // ---- S = Q K^T ----
            float s[8][4];
            #pragma unroll
            for (int t = 0; t < 8; t++) { s[t][0] = 0.f; s[t][1] = 0.f; s[t][2] = 0.f; s[t][3] = 0.f; }

            #pragma unroll
            for (int k8 = 0; k8 < 16; k8 += 2) {   // 8 k-steps of 16
                uint32_t a0, a1, a2, a3;
                ldsm4(a0, a1, a2, a3, swadr(Qb, rowA, k8 + cA));
                #pragma unroll
                for (int p = 0; p < 4; p++) {
                    uint32_t b0, b1, b2, b3;
                    ldsm4(b0, b1, b2, b3, swadr(Kc, rowB + 16 * p, k8 + cB));
                    mma16(s[2 * p],     a0, a1, a2, a3, b0, b1);
                    mma16(s[2 * p + 1], a0, a1, a2, a3, b2, b3);
                }
            }

            // ---- softcap + mask + online softmax (in registers) ----
            float rmax0 = -1e30f, rmax1 = -1e30f;
            #pragma unroll
            for (int t = 0; t < 8; t++) {
                const int jg = j0 + 8 * t + 2 * tg;
                float v0 = 50.f * tanh_fast(s[t][0] * 0.02f);
                float v1 = 50.f * tanh_fast(s[t][1] * 0.02f);
                float v2 = 50.f * tanh_fast(s[t][2] * 0.02f);
                float v3 = 50.f * tanh_fast(s[t][3] * 0.02f);
                bool ok0 = (jg     <= ig0) && (ig0 - jg     < WIN);
                bool ok1 = (jg + 1 <= ig0) && (ig0 - jg - 1 < WIN);
                bool ok2 = (jg     <= ig1) && (ig1 - jg     < WIN);
                bool ok3 = (jg + 1 <= ig1) && (ig1 - jg - 1 < WIN);
                s[t][0] = ok0 ? v0 : -1e30f;
                s[t][1] = ok1 ? v1 : -1e30f;
                s[t][2] = ok2 ? v2 : -1e30f;
                s[t][3] = ok3 ? v3 : -1e30f;
                rmax0 = fmaxf(rmax0, fmaxf(s[t][0], s[t][1]));
                rmax1 = fmaxf(rmax1, fmaxf(s[t][2], s[t][3]));
            }
            rmax0 = fmaxf(rmax0, __shfl_xor_sync(0xffffffffu, rmax0, 1));
            rmax0 = fmaxf(rmax0, __shfl_xor_sync(0xffffffffu, rmax0, 2));
            rmax1 = fmaxf(rmax1, __shfl_xor_sync(0xffffffffu, rmax1, 1));
            rmax1 = fmaxf(rmax1, __shfl_xor_sync(0xffffffffu, rmax1, 2));

            const float m0n = fmaxf(m0, rmax0);
            const float m1n = fmaxf(m1, rmax1);
            const float al0 = ex2((m0 - m0n) * LOG2E);
            const float al1 = ex2((m1 - m1n) * LOG2E);
            m0 = m0n; m1 = m1n;

            float ls0 = 0.f, ls1 = 0.f;
            #pragma unroll
            for (int t = 0; t < 8; t++) {
                float p0 = (s[t][0] > -1e29f) ? ex2((s[t][0] - m0n) * LOG2E) : 0.f;
                float p1 = (s[t][1] > -1e29f) ? ex2((s[t][1] - m0n) * LOG2E) : 0.f;
                float p2 = (s[t][2] > -1e29f) ? ex2((s[t][2] - m1n) * LOG2E) : 0.f;
                float p3 = (s[t][3] > -1e29f) ? ex2((s[t][3] - m1n) * LOG2E) : 0.f;
                s[t][0] = p0; s[t][1] = p1; s[t][2] = p2; s[t][3] = p3;
                ls0 += p0 + p1; ls1 += p2 + p3;
            }
            ls0 += __shfl_xor_sync(0xffffffffu, ls0, 1);
            ls0 += __shfl_xor_sync(0xffffffffu, ls0, 2);
            ls1 += __shfl_xor_sync(0xffffffffu, ls1, 1);
            ls1 += __shfl_xor_sync(0xffffffffu, ls1, 2);
            l0 = l0 * al0 + ls0;
            l1 = l1 * al1 + ls1;

            #pragma unroll
            for (int t = 0; t < 16; t++) {
                o[t][0] *= al0; o[t][1] *= al0; o[t][2] *= al1; o[t][3] *= al1;
            }

            // ---- PV: A from S regs (pack to fp16), B via ldmatrix.trans ----
            #pragma unroll
            for (int u = 0; u < 4; u++) {
                const uint32_t a0 = pk(s[2*u][0],   s[2*u][1]);
                const uint32_t a1 = pk(s[2*u][2],   s[2*u][3]);
                const uint32_t a2 = pk(s[2*u+1][0], s[2*u+1][1]);
                const uint32_t a3 = pk(s[2*u+1][2], s[2*u+1][3]);
                #pragma unroll
                for (int p = 0; p < 8; p++) {
                    uint32_t b0, b1, b2, b3;
                    ldsm4t(b0, b1, b2, b3, swadr(Vc, 16 * u + rowV_, 2 * p + cV));
                    mma16(o[2 * p],     a0, a1, a2, a3, b0, b1);
                    mma16(o[2 * p + 1], a0, a1, a2, a3, b2, b3);
                }
            }
        }

        // ---- store prefetched tile into the other buffer ----
        if (kt < hi) {
            const uint32_t Kn = Kb + (cur ^ 1) * KBYTES;
            const uint32_t Vn = Vb + (cur ^ 1) * KBYTES;
            #pragma unroll
            for (int it = 0; it < 4; it++) {
                const int r = lr + 16 * it;
                uint4 uk, uv;
                uk.x = pk(kr[2*it].x, kr[2*it].y);     uk.y = pk(kr[2*it].z, kr[2*it].w);
                uk.z = pk(kr[2*it+1].x, kr[2*it+1].y); uk.w = pk(kr[2*it+1].z, kr[2*it+1].w);
                uv.x = pk(vr[2*it].x, vr[2*it].y);     uv.y = pk(vr[2*it].z, vr[2*it].w);
                uv.z = pk(vr[2*it+1].x, vr[2*it+1].y); uv.w = pk(vr[2*it+1].z, vr[2*it+1].w);
                asm volatile("st.shared.v4.b32 [%0], {%1,%2,%3,%4};"
                             :: "r"(swadr(Kn, r, lc)), "r"(uk.x), "r"(uk.y), "r"(uk.z), "r"(uk.w));
                asm volatile("st.shared.v4.b32 [%0], {%1,%2,%3,%4};"
                             :: "r"(swadr(Vn, r, lc)), "r"(uv.x), "r"(uv.y), "r"(uv.z), "r"(uv.w));
            }
        }
        __syncthreads();
    }

    // ---- write output ----
    const float inv0 = 1.f / l0;
    const float inv1 = 1.f / l1;
    const size_t base0 = ((size_t)((b * SS + ig0) * HH + h)) * DD;
    const size_t base1 = ((size_t)((b * SS + ig1) * HH + h)) * DD;
    #pragma unroll
    for (int t = 0; t < 16; t++) {
        const int col = 8 * t + 2 * tg;
        *(float2*)&out[base0 + col] = make_float2(o[t][0] * inv0, o[t][1] * inv0);
        *(float2*)&out[base1 + col] = make_float2(o[t][2] * inv1, o[t][3] * inv1);
    }
}

extern "C" void kernel_launch(void* const* d_in, const int* in_sizes, int n_in,
                              void* d_out, int out_size)
{
    const float* q = (const float*)d_in[0];   // query  [4096,32,128]
    const float* k = (const float*)d_in[1];   // key    [4096, 8,128]
    const float* v = (const float*)d_in[2];   // value  [4096, 8,128]
    // d_in[3..5] (caches + block table) do not affect the output: the cache
    // write-then-gather of the same permutation blocks returns key/value unchanged.
    float* out = (float*)d_out;

    cudaFuncSetAttribute(attn_kernel,
                         cudaFuncAttributeMaxDynamicSharedMemorySize,
                         SMEM_BYTES);

    dim3 grid(SS / QTILE, HH, BB);   // 8 x 32 x 4 = 1024 blocks
    attn_kernel<<<grid, NT, SMEM_BYTES>>>(q, k, v, out);
}